// round 15
// baseline (speedup 1.0000x reference)
#include <cuda_runtime.h>

#define C 128
#define MAXN 50000
#define MAXE 1600000

typedef unsigned long long ull;

// Scratch (no cudaMalloc allowed)
__device__ __align__(16) float g_h [MAXN * C];   // current node features
__device__ __align__(16) float g_hw[MAXN * C];   // h @ W   (also P = h @ W_top)
__device__ __align__(16) float g_q [MAXN * C];   // Q = h @ W_bot
__device__ int   g_deg[MAXN];
__device__ float g_dis[MAXN];
__device__ int   g_ptr[MAXN + 1];
__device__ int   g_cur[MAXN];
__device__ int   g_src[MAXE];

// packed f32x2 FMA: d = a*b + c elementwise on two fp32 lanes (SASS FFMA2)
__device__ __forceinline__ ull ffma2(ull a, ull b, ull c) {
    ull d;
    asm("fma.rn.f32x2 %0, %1, %2, %3;" : "=l"(d) : "l"(a), "l"(b), "l"(c));
    return d;
}
__device__ __forceinline__ float f2sum(ull v) {
    float lo, hi;
    asm("mov.b64 {%0, %1}, %2;" : "=f"(lo), "=f"(hi) : "l"(v));
    return lo + hi;
}

// ---------------------------------------------------------------------------
// CSR build
// ---------------------------------------------------------------------------
__global__ void k_init(int N) {
    int i = blockIdx.x * blockDim.x + threadIdx.x;
    if (i < N) { g_deg[i] = 1; g_cur[i] = 0; }   // deg starts at 1 (self loop)
}

__global__ void k_count(const int* __restrict__ col, int E) {
    int e = blockIdx.x * blockDim.x + threadIdx.x;
    if (e < E) atomicAdd(&g_deg[col[e]], 1);
}

__global__ void k_scan(int N) {
    const int T = 1024;
    int tid = threadIdx.x;
    int chunk = (N + T - 1) / T;
    int beg = tid * chunk;
    int end = min(beg + chunk, N);
    int s = 0;
    for (int i = beg; i < end; i++) s += g_deg[i] - 1;
    __shared__ int sums[T];
    sums[tid] = s;
    __syncthreads();
    for (int off = 1; off < T; off <<= 1) {
        int v = (tid >= off) ? sums[tid - off] : 0;
        __syncthreads();
        sums[tid] += v;
        __syncthreads();
    }
    int run = (tid > 0) ? sums[tid - 1] : 0;
    for (int i = beg; i < end; i++) {
        g_ptr[i] = run;
        int d = g_deg[i];
        run += d - 1;
        g_dis[i] = rsqrtf((float)d);
    }
    if (tid == T - 1) g_ptr[N] = sums[T - 1];
}

__global__ void k_fill(const int* __restrict__ row, const int* __restrict__ col, int E) {
    int e = blockIdx.x * blockDim.x + threadIdx.x;
    if (e < E) {
        int c = col[e];
        int pos = atomicAdd(&g_cur[c], 1);
        g_src[g_ptr[c] + pos] = row[e];
    }
}

// ---------------------------------------------------------------------------
// Stage W[128][128] (row-major [k][c]) into smem as k-pair-interleaved f32x2:
// sWp[k2*128 + c] (8B units) = (W[2*k2][c], W[2*k2+1][c])
// ---------------------------------------------------------------------------
__device__ __forceinline__ void stage_w_packed(const float* __restrict__ W,
                                               float* sWp, int tid) {
    const float4* W4 = (const float4*)W;
    #pragma unroll
    for (int i = tid; i < 2048; i += 256) {
        int k2 = i >> 5, j = i & 31;
        float4 wlo = W4[(2 * k2) * 32 + j];
        float4 whi = W4[(2 * k2 + 1) * 32 + j];
        float2* dst = (float2*)&sWp[(k2 * 128 + j * 4) * 2];
        dst[0] = make_float2(wlo.x, whi.x);
        dst[1] = make_float2(wlo.y, whi.y);
        dst[2] = make_float2(wlo.z, whi.z);
        dst[3] = make_float2(wlo.w, whi.w);
    }
}

// ---------------------------------------------------------------------------
// Inner-product core: 64 rows x 128 cols per 256-thread block.
// warp = 8 rows (ty=tid>>5), lane tx owns cols {tx, 32+tx, 64+tx, 96+tx}.
// Per k4-step/thread: 8x LDS.128 u (warp-broadcast) + 8x LDS.64 w + 64 FFMA2.
// ---------------------------------------------------------------------------

// GEMM: Out[M,128] = A[M,128] @ W[128,128]
__global__ __launch_bounds__(256, 2)
void k_gemm(const float* __restrict__ A, const float* __restrict__ W,
            float* __restrict__ Out, int M) {
    extern __shared__ float smem[];
    float* sWp = smem;            // 16384 floats (packed W)
    float* sA  = smem + 16384;    // 64*128 floats
    int tid = threadIdx.x;

    stage_w_packed(W, sWp, tid);

    int m0 = blockIdx.x * 64;
    const float4* A4 = (const float4*)A;
    #pragma unroll
    for (int i = tid; i < 2048; i += 256) {
        int r = i >> 5, c = i & 31;
        int gm = m0 + r;
        float4 v = (gm < M) ? A4[(size_t)gm * 32 + c] : make_float4(0.f, 0.f, 0.f, 0.f);
        *(float4*)&sA[r * 128 + c * 4] = v;
    }
    __syncthreads();

    const ull* sW64 = (const ull*)sWp;
    int ty = tid >> 5, tx = tid & 31;
    ull acc[8][4];
    #pragma unroll
    for (int e = 0; e < 8; e++)
        #pragma unroll
        for (int j = 0; j < 4; j++) acc[e][j] = 0ULL;

    #pragma unroll 2
    for (int k = 0; k < 128; k += 4) {
        int k2 = k >> 1;
        ull wA0 = sW64[(k2 + 0) * 128 + tx];
        ull wB0 = sW64[(k2 + 0) * 128 + 32 + tx];
        ull wC0 = sW64[(k2 + 0) * 128 + 64 + tx];
        ull wD0 = sW64[(k2 + 0) * 128 + 96 + tx];
        ull wA1 = sW64[(k2 + 1) * 128 + tx];
        ull wB1 = sW64[(k2 + 1) * 128 + 32 + tx];
        ull wC1 = sW64[(k2 + 1) * 128 + 64 + tx];
        ull wD1 = sW64[(k2 + 1) * 128 + 96 + tx];
        #pragma unroll
        for (int e = 0; e < 8; e++) {
            ulonglong2 u = *(const ulonglong2*)&sA[(ty * 8 + e) * 128 + k];
            acc[e][0] = ffma2(u.x, wA0, acc[e][0]);
            acc[e][1] = ffma2(u.x, wB0, acc[e][1]);
            acc[e][2] = ffma2(u.x, wC0, acc[e][2]);
            acc[e][3] = ffma2(u.x, wD0, acc[e][3]);
            acc[e][0] = ffma2(u.y, wA1, acc[e][0]);
            acc[e][1] = ffma2(u.y, wB1, acc[e][1]);
            acc[e][2] = ffma2(u.y, wC1, acc[e][2]);
            acc[e][3] = ffma2(u.y, wD1, acc[e][3]);
        }
    }
    #pragma unroll
    for (int e = 0; e < 8; e++) {
        int gm = m0 + ty * 8 + e;
        if (gm < M) {
            float* o = &Out[(size_t)gm * 128];
            o[tx]      = f2sum(acc[e][0]);
            o[32 + tx] = f2sum(acc[e][1]);
            o[64 + tx] = f2sum(acc[e][2]);
            o[96 + tx] = f2sum(acc[e][3]);
        }
    }
}

// ---------------------------------------------------------------------------
// Aggregation: one warp per node (L2 gather bound).
// ---------------------------------------------------------------------------
__global__ void k_agg(const float* __restrict__ hw, const float* __restrict__ bias,
                      int N, int residual) {
    int warp = (blockIdx.x * blockDim.x + threadIdx.x) >> 5;
    int lane = threadIdx.x & 31;
    if (warp >= N) return;
    int beg = g_ptr[warp], end = g_ptr[warp + 1];
    float ax = 0.f, ay = 0.f, az = 0.f, aw = 0.f;
    int j = beg;
    for (; j + 3 < end; j += 4) {
        int s0 = g_src[j], s1 = g_src[j + 1], s2 = g_src[j + 2], s3 = g_src[j + 3];
        float n0 = g_dis[s0], n1 = g_dis[s1], n2 = g_dis[s2], n3 = g_dis[s3];
        float4 v0 = *(const float4*)&hw[(size_t)s0 * 128 + lane * 4];
        float4 v1 = *(const float4*)&hw[(size_t)s1 * 128 + lane * 4];
        float4 v2 = *(const float4*)&hw[(size_t)s2 * 128 + lane * 4];
        float4 v3 = *(const float4*)&hw[(size_t)s3 * 128 + lane * 4];
        ax += n0 * v0.x + n1 * v1.x + n2 * v2.x + n3 * v3.x;
        ay += n0 * v0.y + n1 * v1.y + n2 * v2.y + n3 * v3.y;
        az += n0 * v0.z + n1 * v1.z + n2 * v2.z + n3 * v3.z;
        aw += n0 * v0.w + n1 * v1.w + n2 * v2.w + n3 * v3.w;
    }
    for (; j < end; j++) {
        int s = g_src[j];
        float n = g_dis[s];
        float4 v = *(const float4*)&hw[(size_t)s * 128 + lane * 4];
        ax += n * v.x; ay += n * v.y; az += n * v.z; aw += n * v.w;
    }
    float di = g_dis[warp];
    float sc = di * di;
    float4 sv = *(const float4*)&hw[(size_t)warp * 128 + lane * 4];
    ax = ax * di + sv.x * sc;
    ay = ay * di + sv.y * sc;
    az = az * di + sv.z * sc;
    aw = aw * di + sv.w * sc;
    float4 b = *(const float4*)&bias[lane * 4];
    ax += b.x; ay += b.y; az += b.z; aw += b.w;
    if (residual) {
        float4 hv = *(const float4*)&g_h[(size_t)warp * 128 + lane * 4];
        ax += hv.x; ay += hv.y; az += hv.z; aw += hv.w;
    }
    ax = fmaxf(ax, 0.f); ay = fmaxf(ay, 0.f);
    az = fmaxf(az, 0.f); aw = fmaxf(aw, 0.f);
    *(float4*)&g_h[(size_t)warp * 128 + lane * 4] = make_float4(ax, ay, az, aw);
}

// ---------------------------------------------------------------------------
// Edge MLP: u = relu(P[src]+Q[dst]+b0); v = relu(u@W1+b1); out = v.w2 + b2
// 64 edges per 256-thread block, FFMA2 core.
// ---------------------------------------------------------------------------
__global__ __launch_bounds__(256, 2)
void k_edge(const int* __restrict__ row, const int* __restrict__ col,
            const float* __restrict__ b0, const float* __restrict__ W1,
            const float* __restrict__ b1, const float* __restrict__ w2,
            const float* __restrict__ b2, float* __restrict__ out, int E) {
    extern __shared__ float smem[];
    float* sWp = smem;            // 16384 floats (packed W1)
    float* sU  = smem + 16384;    // 64*128 floats
    int tid = threadIdx.x;

    stage_w_packed(W1, sWp, tid);

    int e0 = blockIdx.x * 64;
    {
        int le = tid >> 2;       // local edge 0..63
        int seg = tid & 3;       // 4 threads per edge row
        int e = e0 + le;
        if (e < E) {
            int s = row[e], d = col[e];
            const float4* Pr = (const float4*)&g_hw[(size_t)s * 128];
            const float4* Qr = (const float4*)&g_q[(size_t)d * 128];
            const float4* B = (const float4*)b0;
            #pragma unroll
            for (int i = 0; i < 8; i++) {
                int c4 = i * 4 + seg;
                float4 p = Pr[c4], q = Qr[c4], b = B[c4];
                float4 u;
                u.x = fmaxf(p.x + q.x + b.x, 0.f);
                u.y = fmaxf(p.y + q.y + b.y, 0.f);
                u.z = fmaxf(p.z + q.z + b.z, 0.f);
                u.w = fmaxf(p.w + q.w + b.w, 0.f);
                *(float4*)&sU[le * 128 + c4 * 4] = u;
            }
        }
    }
    __syncthreads();

    const ull* sW64 = (const ull*)sWp;
    int ty = tid >> 5, tx = tid & 31;
    ull acc[8][4];
    #pragma unroll
    for (int e = 0; e < 8; e++)
        #pragma unroll
        for (int j = 0; j < 4; j++) acc[e][j] = 0ULL;

    #pragma unroll 2
    for (int k = 0; k < 128; k += 4) {
        int k2 = k >> 1;
        ull wA0 = sW64[(k2 + 0) * 128 + tx];
        ull wB0 = sW64[(k2 + 0) * 128 + 32 + tx];
        ull wC0 = sW64[(k2 + 0) * 128 + 64 + tx];
        ull wD0 = sW64[(k2 + 0) * 128 + 96 + tx];
        ull wA1 = sW64[(k2 + 1) * 128 + tx];
        ull wB1 = sW64[(k2 + 1) * 128 + 32 + tx];
        ull wC1 = sW64[(k2 + 1) * 128 + 64 + tx];
        ull wD1 = sW64[(k2 + 1) * 128 + 96 + tx];
        #pragma unroll
        for (int e = 0; e < 8; e++) {
            ulonglong2 u = *(const ulonglong2*)&sU[(ty * 8 + e) * 128 + k];
            acc[e][0] = ffma2(u.x, wA0, acc[e][0]);
            acc[e][1] = ffma2(u.x, wB0, acc[e][1]);
            acc[e][2] = ffma2(u.x, wC0, acc[e][2]);
            acc[e][3] = ffma2(u.x, wD0, acc[e][3]);
            acc[e][0] = ffma2(u.y, wA1, acc[e][0]);
            acc[e][1] = ffma2(u.y, wB1, acc[e][1]);
            acc[e][2] = ffma2(u.y, wC1, acc[e][2]);
            acc[e][3] = ffma2(u.y, wD1, acc[e][3]);
        }
    }

    // epilogue: v = relu(acc + b1); out = v . w2 + b2 (32-lane reduction)
    float b1a = b1[tx], b1b = b1[32 + tx], b1c = b1[64 + tx], b1d = b1[96 + tx];
    float w2a = w2[tx], w2b = w2[32 + tx], w2c = w2[64 + tx], w2d = w2[96 + tx];
    float bias2 = b2[0];
    #pragma unroll
    for (int e = 0; e < 8; e++) {
        float r = fmaxf(f2sum(acc[e][0]) + b1a, 0.f) * w2a
                + fmaxf(f2sum(acc[e][1]) + b1b, 0.f) * w2b
                + fmaxf(f2sum(acc[e][2]) + b1c, 0.f) * w2c
                + fmaxf(f2sum(acc[e][3]) + b1d, 0.f) * w2d;
        #pragma unroll
        for (int off = 16; off; off >>= 1)
            r += __shfl_down_sync(0xffffffffu, r, off);
        if (tx == 0) {
            int ee = e0 + ty * 8 + e;
            if (ee < E) out[ee] = r + bias2;
        }
    }
}

// ---------------------------------------------------------------------------
extern "C" void kernel_launch(void* const* d_in, const int* in_sizes, int n_in,
                              void* d_out, int out_size) {
    const float* x       = (const float*)d_in[0];
    const int*   ei      = (const int*)  d_in[1];
    const float* convs_W = (const float*)d_in[2];
    const float* convs_b = (const float*)d_in[3];
    const float* fc0_W   = (const float*)d_in[4];
    const float* fc0_b   = (const float*)d_in[5];
    const float* fc1_W   = (const float*)d_in[6];
    const float* fc1_b   = (const float*)d_in[7];
    const float* fc2_W   = (const float*)d_in[8];
    const float* fc2_b   = (const float*)d_in[9];
    float* out = (float*)d_out;

    int N = in_sizes[0] / C;
    int E = in_sizes[1] / 2;
    int n_layers = in_sizes[2] / (C * C);
    const int* row = ei;
    const int* col = ei + E;

    const int SMEM_TILE = (16384 + 8192) * 4;   // 96 KB
    cudaFuncSetAttribute(k_gemm, cudaFuncAttributeMaxDynamicSharedMemorySize, SMEM_TILE);
    cudaFuncSetAttribute(k_edge, cudaFuncAttributeMaxDynamicSharedMemorySize, SMEM_TILE);

    float *p_h, *p_hw, *p_q;
    cudaGetSymbolAddress((void**)&p_h,  g_h);
    cudaGetSymbolAddress((void**)&p_hw, g_hw);
    cudaGetSymbolAddress((void**)&p_q,  g_q);

    // CSR build (per-launch; no state may persist across calls)
    k_init <<<(N + 255) / 256, 256>>>(N);
    k_count<<<(E + 255) / 256, 256>>>(col, E);
    k_scan <<<1, 1024>>>(N);
    k_fill <<<(E + 255) / 256, 256>>>(row, col, E);

    int gb = (N + 63) / 64;
    int ab = (N * 32 + 255) / 256;

    // layer 0 (input = x, no residual)
    k_gemm<<<gb, 256, SMEM_TILE>>>(x, convs_W, p_hw, N);
    k_agg <<<ab, 256>>>(p_hw, convs_b, N, 0);

    // layers 1..L-1 (residual)
    for (int l = 1; l < n_layers; l++) {
        k_gemm<<<gb, 256, SMEM_TILE>>>(p_h, convs_W + (size_t)l * C * C, p_hw, N);
        k_agg <<<ab, 256>>>(p_hw, convs_b + (size_t)l * C, N, 1);
    }

    // fc0 factorization: P = h @ W_top (-> g_hw), Q = h @ W_bot (-> g_q)
    k_gemm<<<gb, 256, SMEM_TILE>>>(p_h, fc0_W,         p_hw, N);
    k_gemm<<<gb, 256, SMEM_TILE>>>(p_h, fc0_W + C * C, p_q,  N);

    // fused per-edge MLP (fc0-combine + relu + fc1 + relu + fc2)
    k_edge<<<(E + 63) / 64, 256, SMEM_TILE>>>(row, col, fc0_b, fc1_W, fc1_b,
                                              fc2_W, fc2_b, out, E);
}

// round 16
// speedup vs baseline: 1.0008x; 1.0008x over previous
#include <cuda_runtime.h>

#define C 128
#define MAXN 50000
#define MAXE 1600000

typedef unsigned long long ull;

// Scratch (no cudaMalloc allowed)
__device__ __align__(16) float g_h [MAXN * C];   // current node features
__device__ __align__(16) float g_hw[MAXN * C];   // h @ W   (also P = h @ W_top)
__device__ __align__(16) float g_q [MAXN * C];   // Q = h @ W_bot
__device__ int   g_deg[MAXN];
__device__ float g_dis[MAXN];
__device__ int   g_ptr[MAXN + 1];
__device__ int   g_cur[MAXN];
__device__ int   g_src[MAXE];

// packed f32x2 FMA: d = a*b + c elementwise on two fp32 lanes (SASS FFMA2)
__device__ __forceinline__ ull ffma2(ull a, ull b, ull c) {
    ull d;
    asm("fma.rn.f32x2 %0, %1, %2, %3;" : "=l"(d) : "l"(a), "l"(b), "l"(c));
    return d;
}
__device__ __forceinline__ float f2sum(ull v) {
    float lo, hi;
    asm("mov.b64 {%0, %1}, %2;" : "=f"(lo), "=f"(hi) : "l"(v));
    return lo + hi;
}

// ---------------------------------------------------------------------------
// CSR build
// ---------------------------------------------------------------------------
__global__ void k_init(int N) {
    int i = blockIdx.x * blockDim.x + threadIdx.x;
    if (i < N) { g_deg[i] = 1; g_cur[i] = 0; }   // deg starts at 1 (self loop)
}

__global__ void k_count(const int* __restrict__ col, int E) {
    int e = blockIdx.x * blockDim.x + threadIdx.x;
    if (e < E) atomicAdd(&g_deg[col[e]], 1);
}

__global__ void k_scan(int N) {
    const int T = 1024;
    int tid = threadIdx.x;
    int chunk = (N + T - 1) / T;
    int beg = tid * chunk;
    int end = min(beg + chunk, N);
    int s = 0;
    for (int i = beg; i < end; i++) s += g_deg[i] - 1;
    __shared__ int sums[T];
    sums[tid] = s;
    __syncthreads();
    for (int off = 1; off < T; off <<= 1) {
        int v = (tid >= off) ? sums[tid - off] : 0;
        __syncthreads();
        sums[tid] += v;
        __syncthreads();
    }
    int run = (tid > 0) ? sums[tid - 1] : 0;
    for (int i = beg; i < end; i++) {
        g_ptr[i] = run;
        int d = g_deg[i];
        run += d - 1;
        g_dis[i] = rsqrtf((float)d);
    }
    if (tid == T - 1) g_ptr[N] = sums[T - 1];
}

__global__ void k_fill(const int* __restrict__ row, const int* __restrict__ col, int E) {
    int e = blockIdx.x * blockDim.x + threadIdx.x;
    if (e < E) {
        int c = col[e];
        int pos = atomicAdd(&g_cur[c], 1);
        g_src[g_ptr[c] + pos] = row[e];
    }
}

// ---------------------------------------------------------------------------
// Stage W[128][128] (row-major [k][c]) into smem as k-pair-interleaved f32x2:
// sWp[k2*128 + c] (8B units) = (W[2*k2][c], W[2*k2+1][c])
// ---------------------------------------------------------------------------
__device__ __forceinline__ void stage_w_packed(const float* __restrict__ W,
                                               float* sWp, int tid) {
    const float4* W4 = (const float4*)W;
    #pragma unroll
    for (int i = tid; i < 2048; i += 256) {
        int k2 = i >> 5, j = i & 31;
        float4 wlo = W4[(2 * k2) * 32 + j];
        float4 whi = W4[(2 * k2 + 1) * 32 + j];
        float2* dst = (float2*)&sWp[(k2 * 128 + j * 4) * 2];
        dst[0] = make_float2(wlo.x, whi.x);
        dst[1] = make_float2(wlo.y, whi.y);
        dst[2] = make_float2(wlo.z, whi.z);
        dst[3] = make_float2(wlo.w, whi.w);
    }
}

// ---------------------------------------------------------------------------
// Inner-product core: 64 rows x 128 cols per 256-thread block.
// warp = 8 rows (ty=tid>>5), lane tx owns cols {tx, 32+tx, 64+tx, 96+tx}.
// Per k4-step/thread: 8x LDS.128 u (warp-broadcast) + 8x LDS.64 w + 64 FFMA2.
// ---------------------------------------------------------------------------

// GEMM: Out[M,128] = A[M,128] @ W[128,128]
__global__ __launch_bounds__(256, 2)
void k_gemm(const float* __restrict__ A, const float* __restrict__ W,
            float* __restrict__ Out, int M) {
    extern __shared__ float smem[];
    float* sWp = smem;            // 16384 floats (packed W)
    float* sA  = smem + 16384;    // 64*128 floats
    int tid = threadIdx.x;

    stage_w_packed(W, sWp, tid);

    int m0 = blockIdx.x * 64;
    const float4* A4 = (const float4*)A;
    #pragma unroll
    for (int i = tid; i < 2048; i += 256) {
        int r = i >> 5, c = i & 31;
        int gm = m0 + r;
        float4 v = (gm < M) ? A4[(size_t)gm * 32 + c] : make_float4(0.f, 0.f, 0.f, 0.f);
        *(float4*)&sA[r * 128 + c * 4] = v;
    }
    __syncthreads();

    const ull* sW64 = (const ull*)sWp;
    int ty = tid >> 5, tx = tid & 31;
    ull acc[8][4];
    #pragma unroll
    for (int e = 0; e < 8; e++)
        #pragma unroll
        for (int j = 0; j < 4; j++) acc[e][j] = 0ULL;

    #pragma unroll 2
    for (int k = 0; k < 128; k += 4) {
        int k2 = k >> 1;
        ull wA0 = sW64[(k2 + 0) * 128 + tx];
        ull wB0 = sW64[(k2 + 0) * 128 + 32 + tx];
        ull wC0 = sW64[(k2 + 0) * 128 + 64 + tx];
        ull wD0 = sW64[(k2 + 0) * 128 + 96 + tx];
        ull wA1 = sW64[(k2 + 1) * 128 + tx];
        ull wB1 = sW64[(k2 + 1) * 128 + 32 + tx];
        ull wC1 = sW64[(k2 + 1) * 128 + 64 + tx];
        ull wD1 = sW64[(k2 + 1) * 128 + 96 + tx];
        #pragma unroll
        for (int e = 0; e < 8; e++) {
            ulonglong2 u = *(const ulonglong2*)&sA[(ty * 8 + e) * 128 + k];
            acc[e][0] = ffma2(u.x, wA0, acc[e][0]);
            acc[e][1] = ffma2(u.x, wB0, acc[e][1]);
            acc[e][2] = ffma2(u.x, wC0, acc[e][2]);
            acc[e][3] = ffma2(u.x, wD0, acc[e][3]);
            acc[e][0] = ffma2(u.y, wA1, acc[e][0]);
            acc[e][1] = ffma2(u.y, wB1, acc[e][1]);
            acc[e][2] = ffma2(u.y, wC1, acc[e][2]);
            acc[e][3] = ffma2(u.y, wD1, acc[e][3]);
        }
    }
    #pragma unroll
    for (int e = 0; e < 8; e++) {
        int gm = m0 + ty * 8 + e;
        if (gm < M) {
            float* o = &Out[(size_t)gm * 128];
            o[tx]      = f2sum(acc[e][0]);
            o[32 + tx] = f2sum(acc[e][1]);
            o[64 + tx] = f2sum(acc[e][2]);
            o[96 + tx] = f2sum(acc[e][3]);
        }
    }
}

// ---------------------------------------------------------------------------
// Aggregation: one warp per node (L2 gather bound).
// ---------------------------------------------------------------------------
__global__ void k_agg(const float* __restrict__ hw, const float* __restrict__ bias,
                      int N, int residual) {
    int warp = (blockIdx.x * blockDim.x + threadIdx.x) >> 5;
    int lane = threadIdx.x & 31;
    if (warp >= N) return;
    int beg = g_ptr[warp], end = g_ptr[warp + 1];
    float ax = 0.f, ay = 0.f, az = 0.f, aw = 0.f;
    int j = beg;
    for (; j + 3 < end; j += 4) {
        int s0 = g_src[j], s1 = g_src[j + 1], s2 = g_src[j + 2], s3 = g_src[j + 3];
        float n0 = g_dis[s0], n1 = g_dis[s1], n2 = g_dis[s2], n3 = g_dis[s3];
        float4 v0 = *(const float4*)&hw[(size_t)s0 * 128 + lane * 4];
        float4 v1 = *(const float4*)&hw[(size_t)s1 * 128 + lane * 4];
        float4 v2 = *(const float4*)&hw[(size_t)s2 * 128 + lane * 4];
        float4 v3 = *(const float4*)&hw[(size_t)s3 * 128 + lane * 4];
        ax += n0 * v0.x + n1 * v1.x + n2 * v2.x + n3 * v3.x;
        ay += n0 * v0.y + n1 * v1.y + n2 * v2.y + n3 * v3.y;
        az += n0 * v0.z + n1 * v1.z + n2 * v2.z + n3 * v3.z;
        aw += n0 * v0.w + n1 * v1.w + n2 * v2.w + n3 * v3.w;
    }
    for (; j < end; j++) {
        int s = g_src[j];
        float n = g_dis[s];
        float4 v = *(const float4*)&hw[(size_t)s * 128 + lane * 4];
        ax += n * v.x; ay += n * v.y; az += n * v.z; aw += n * v.w;
    }
    float di = g_dis[warp];
    float sc = di * di;
    float4 sv = *(const float4*)&hw[(size_t)warp * 128 + lane * 4];
    ax = ax * di + sv.x * sc;
    ay = ay * di + sv.y * sc;
    az = az * di + sv.z * sc;
    aw = aw * di + sv.w * sc;
    float4 b = *(const float4*)&bias[lane * 4];
    ax += b.x; ay += b.y; az += b.z; aw += b.w;
    if (residual) {
        float4 hv = *(const float4*)&g_h[(size_t)warp * 128 + lane * 4];
        ax += hv.x; ay += hv.y; az += hv.z; aw += hv.w;
    }
    ax = fmaxf(ax, 0.f); ay = fmaxf(ay, 0.f);
    az = fmaxf(az, 0.f); aw = fmaxf(aw, 0.f);
    *(float4*)&g_h[(size_t)warp * 128 + lane * 4] = make_float4(ax, ay, az, aw);
}

// ---------------------------------------------------------------------------
// Edge MLP: u = relu(P[src]+Q[dst]+b0); v = relu(u@W1+b1); out = v.w2 + b2
// 64 edges per 256-thread block, FFMA2 core.
// ---------------------------------------------------------------------------
__global__ __launch_bounds__(256, 2)
void k_edge(const int* __restrict__ row, const int* __restrict__ col,
            const float* __restrict__ b0, const float* __restrict__ W1,
            const float* __restrict__ b1, const float* __restrict__ w2,
            const float* __restrict__ b2, float* __restrict__ out, int E) {
    extern __shared__ float smem[];
    float* sWp = smem;            // 16384 floats (packed W1)
    float* sU  = smem + 16384;    // 64*128 floats
    int tid = threadIdx.x;

    stage_w_packed(W1, sWp, tid);

    int e0 = blockIdx.x * 64;
    {
        int le = tid >> 2;       // local edge 0..63
        int seg = tid & 3;       // 4 threads per edge row
        int e = e0 + le;
        if (e < E) {
            int s = row[e], d = col[e];
            const float4* Pr = (const float4*)&g_hw[(size_t)s * 128];
            const float4* Qr = (const float4*)&g_q[(size_t)d * 128];
            const float4* B = (const float4*)b0;
            #pragma unroll
            for (int i = 0; i < 8; i++) {
                int c4 = i * 4 + seg;
                float4 p = Pr[c4], q = Qr[c4], b = B[c4];
                float4 u;
                u.x = fmaxf(p.x + q.x + b.x, 0.f);
                u.y = fmaxf(p.y + q.y + b.y, 0.f);
                u.z = fmaxf(p.z + q.z + b.z, 0.f);
                u.w = fmaxf(p.w + q.w + b.w, 0.f);
                *(float4*)&sU[le * 128 + c4 * 4] = u;
            }
        }
    }
    __syncthreads();

    const ull* sW64 = (const ull*)sWp;
    int ty = tid >> 5, tx = tid & 31;
    ull acc[8][4];
    #pragma unroll
    for (int e = 0; e < 8; e++)
        #pragma unroll
        for (int j = 0; j < 4; j++) acc[e][j] = 0ULL;

    #pragma unroll 2
    for (int k = 0; k < 128; k += 4) {
        int k2 = k >> 1;
        ull wA0 = sW64[(k2 + 0) * 128 + tx];
        ull wB0 = sW64[(k2 + 0) * 128 + 32 + tx];
        ull wC0 = sW64[(k2 + 0) * 128 + 64 + tx];
        ull wD0 = sW64[(k2 + 0) * 128 + 96 + tx];
        ull wA1 = sW64[(k2 + 1) * 128 + tx];
        ull wB1 = sW64[(k2 + 1) * 128 + 32 + tx];
        ull wC1 = sW64[(k2 + 1) * 128 + 64 + tx];
        ull wD1 = sW64[(k2 + 1) * 128 + 96 + tx];
        #pragma unroll
        for (int e = 0; e < 8; e++) {
            ulonglong2 u = *(const ulonglong2*)&sU[(ty * 8 + e) * 128 + k];
            acc[e][0] = ffma2(u.x, wA0, acc[e][0]);
            acc[e][1] = ffma2(u.x, wB0, acc[e][1]);
            acc[e][2] = ffma2(u.x, wC0, acc[e][2]);
            acc[e][3] = ffma2(u.x, wD0, acc[e][3]);
            acc[e][0] = ffma2(u.y, wA1, acc[e][0]);
            acc[e][1] = ffma2(u.y, wB1, acc[e][1]);
            acc[e][2] = ffma2(u.y, wC1, acc[e][2]);
            acc[e][3] = ffma2(u.y, wD1, acc[e][3]);
        }
    }

    // epilogue: v = relu(acc + b1); out = v . w2 + b2 (32-lane reduction)
    float b1a = b1[tx], b1b = b1[32 + tx], b1c = b1[64 + tx], b1d = b1[96 + tx];
    float w2a = w2[tx], w2b = w2[32 + tx], w2c = w2[64 + tx], w2d = w2[96 + tx];
    float bias2 = b2[0];
    #pragma unroll
    for (int e = 0; e < 8; e++) {
        float r = fmaxf(f2sum(acc[e][0]) + b1a, 0.f) * w2a
                + fmaxf(f2sum(acc[e][1]) + b1b, 0.f) * w2b
                + fmaxf(f2sum(acc[e][2]) + b1c, 0.f) * w2c
                + fmaxf(f2sum(acc[e][3]) + b1d, 0.f) * w2d;
        #pragma unroll
        for (int off = 16; off; off >>= 1)
            r += __shfl_down_sync(0xffffffffu, r, off);
        if (tx == 0) {
            int ee = e0 + ty * 8 + e;
            if (ee < E) out[ee] = r + bias2;
        }
    }
}

// ---------------------------------------------------------------------------
extern "C" void kernel_launch(void* const* d_in, const int* in_sizes, int n_in,
                              void* d_out, int out_size) {
    const float* x       = (const float*)d_in[0];
    const int*   ei      = (const int*)  d_in[1];
    const float* convs_W = (const float*)d_in[2];
    const float* convs_b = (const float*)d_in[3];
    const float* fc0_W   = (const float*)d_in[4];
    const float* fc0_b   = (const float*)d_in[5];
    const float* fc1_W   = (const float*)d_in[6];
    const float* fc1_b   = (const float*)d_in[7];
    const float* fc2_W   = (const float*)d_in[8];
    const float* fc2_b   = (const float*)d_in[9];
    float* out = (float*)d_out;

    int N = in_sizes[0] / C;
    int E = in_sizes[1] / 2;
    int n_layers = in_sizes[2] / (C * C);
    const int* row = ei;
    const int* col = ei + E;

    const int SMEM_TILE = (16384 + 8192) * 4;   // 96 KB
    cudaFuncSetAttribute(k_gemm, cudaFuncAttributeMaxDynamicSharedMemorySize, SMEM_TILE);
    cudaFuncSetAttribute(k_edge, cudaFuncAttributeMaxDynamicSharedMemorySize, SMEM_TILE);

    float *p_h, *p_hw, *p_q;
    cudaGetSymbolAddress((void**)&p_h,  g_h);
    cudaGetSymbolAddress((void**)&p_hw, g_hw);
    cudaGetSymbolAddress((void**)&p_q,  g_q);

    // CSR build (per-launch; no state may persist across calls)
    k_init <<<(N + 255) / 256, 256>>>(N);
    k_count<<<(E + 255) / 256, 256>>>(col, E);
    k_scan <<<1, 1024>>>(N);
    k_fill <<<(E + 255) / 256, 256>>>(row, col, E);

    int gb = (N + 63) / 64;
    int ab = (N * 32 + 255) / 256;

    // layer 0 (input = x, no residual)
    k_gemm<<<gb, 256, SMEM_TILE>>>(x, convs_W, p_hw, N);
    k_agg <<<ab, 256>>>(p_hw, convs_b, N, 0);

    // layers 1..L-1 (residual)
    for (int l = 1; l < n_layers; l++) {
        k_gemm<<<gb, 256, SMEM_TILE>>>(p_h, convs_W + (size_t)l * C * C, p_hw, N);
        k_agg <<<ab, 256>>>(p_hw, convs_b + (size_t)l * C, N, 1);
    }

    // fc0 factorization: P = h @ W_top (-> g_hw), Q = h @ W_bot (-> g_q)
    k_gemm<<<gb, 256, SMEM_TILE>>>(p_h, fc0_W,         p_hw, N);
    k_gemm<<<gb, 256, SMEM_TILE>>>(p_h, fc0_W + C * C, p_q,  N);

    // fused per-edge MLP (fc0-combine + relu + fc1 + relu + fc2)
    k_edge<<<(E + 63) / 64, 256, SMEM_TILE>>>(row, col, fc0_b, fc1_W, fc1_b,
                                              fc2_W, fc2_b, out, E);
}